// round 15
// baseline (speedup 1.0000x reference)
#include <cuda_runtime.h>
#include <cuda_fp16.h>

#define Nn 200000
#define Ee 3200000
#define IND 165
#define HID 64
#define NB1K 196   // ceil(Nn/1024)
#define PK 176     // K padded to 11x16
#define NG 22      // 8-col groups per padded row

#define NTILES 3125        // Nn/64
#define TSPLIT 1568        // chunk-0 tiles
#define NSPLIT (TSPLIT*64) // chunk-0 nodes = 100352

// ---- scratch (no cudaMalloc allowed) ----
__device__ uint4 g_hh0[Nn * 8];   // fp16 h0 rows (64 halves = 8 uint4)
__device__ uint4 g_hh1[Nn * 8];   // fp16 h1 rows
__device__ uint4 g_ag[Nn * 8];    // fp16 aggregated-mean rows
__device__ int   g_degi[Nn];
__device__ int   g_off[Nn];
__device__ int   g_cur[Nn];
__device__ int   g_csr[Ee];
__device__ int   g_bsum[256];
__device__ int   g_bscan[256];

__device__ __forceinline__ unsigned h2u(__half2 h) {
    return *reinterpret_cast<unsigned*>(&h);
}

// =================== degree histogram (int4) ===================
__global__ __launch_bounds__(256) void deg_kernel(const int* __restrict__ dst, int* __restrict__ degi)
{
    int t = blockIdx.x * blockDim.x + threadIdx.x;
    if (t < Ee / 4) {
        int4 d4 = reinterpret_cast<const int4*>(dst)[t];
        atomicAdd(&degi[d4.x], 1);
        atomicAdd(&degi[d4.y], 1);
        atomicAdd(&degi[d4.z], 1);
        atomicAdd(&degi[d4.w], 1);
    }
}

// =================== 2-level exclusive scan ===================
__global__ __launch_bounds__(256) void scan1(const int* __restrict__ degi, int* __restrict__ bsum)
{
    __shared__ int s[256];
    int base = blockIdx.x * 1024 + threadIdx.x * 4;
    int sum = 0;
    #pragma unroll
    for (int i = 0; i < 4; i++) { int n = base + i; if (n < Nn) sum += degi[n]; }
    s[threadIdx.x] = sum; __syncthreads();
    for (int o = 128; o; o >>= 1) {
        if (threadIdx.x < o) s[threadIdx.x] += s[threadIdx.x + o];
        __syncthreads();
    }
    if (threadIdx.x == 0) bsum[blockIdx.x] = s[0];
}

__global__ __launch_bounds__(256) void scan2(const int* __restrict__ bsum, int* __restrict__ bscan)
{
    __shared__ int s[256];
    int v = (threadIdx.x < NB1K) ? bsum[threadIdx.x] : 0;
    s[threadIdx.x] = v; __syncthreads();
    for (int o = 1; o < 256; o <<= 1) {
        int t = (threadIdx.x >= o) ? s[threadIdx.x - o] : 0;
        __syncthreads();
        s[threadIdx.x] += t;
        __syncthreads();
    }
    if (threadIdx.x < NB1K) bscan[threadIdx.x] = s[threadIdx.x] - v;  // exclusive
}

__global__ __launch_bounds__(256) void scan3(const int* __restrict__ degi, const int* __restrict__ bscan,
                                             int* __restrict__ off, int* __restrict__ cur)
{
    __shared__ int s[256];
    int tid = threadIdx.x;
    int base = blockIdx.x * 1024 + tid * 4;
    int d[4]; int sum = 0;
    #pragma unroll
    for (int i = 0; i < 4; i++) { int n = base + i; d[i] = (n < Nn) ? degi[n] : 0; sum += d[i]; }
    s[tid] = sum; __syncthreads();
    for (int o = 1; o < 256; o <<= 1) {
        int t = (tid >= o) ? s[tid - o] : 0;
        __syncthreads();
        s[tid] += t;
        __syncthreads();
    }
    int ex = s[tid] - sum + bscan[blockIdx.x];
    #pragma unroll
    for (int i = 0; i < 4; i++) {
        int n = base + i;
        if (n < Nn) { off[n] = ex; cur[n] = ex; ex += d[i]; }
    }
}

__global__ __launch_bounds__(256) void place_kernel(const int* __restrict__ src, const int* __restrict__ dst,
                                                    int* __restrict__ cur, int* __restrict__ csr)
{
    int t = blockIdx.x * blockDim.x + threadIdx.x;
    if (t < Ee / 4) {
        int4 s4 = reinterpret_cast<const int4*>(src)[t];
        int4 d4 = reinterpret_cast<const int4*>(dst)[t];
        int p;
        p = atomicAdd(&cur[d4.x], 1); csr[p] = s4.x;
        p = atomicAdd(&cur[d4.y], 1); csr[p] = s4.y;
        p = atomicAdd(&cur[d4.z], 1); csr[p] = s4.z;
        p = atomicAdd(&cur[d4.w], 1); csr[p] = s4.w;
    }
}

// ======== gather-mean fp16->fp32->fp16 over node range [nbeg, nend) ========
__device__ __forceinline__ void acc_u4(const uint4& v, float2& a0, float2& a1, float2& a2, float2& a3)
{
    float2 f;
    f = __half22float2(*reinterpret_cast<const __half2*>(&v.x)); a0.x += f.x; a0.y += f.y;
    f = __half22float2(*reinterpret_cast<const __half2*>(&v.y)); a1.x += f.x; a1.y += f.y;
    f = __half22float2(*reinterpret_cast<const __half2*>(&v.z)); a2.x += f.x; a2.y += f.y;
    f = __half22float2(*reinterpret_cast<const __half2*>(&v.w)); a3.x += f.x; a3.y += f.y;
}

__global__ __launch_bounds__(256) void gather_mean_h(
    const int* __restrict__ csr, const int* __restrict__ off, const int* __restrict__ degi,
    const uint4* __restrict__ hh, uint4* __restrict__ ag, int nbeg, int nend)
{
    int node = nbeg + (int)((blockIdx.x * (unsigned)blockDim.x + threadIdx.x) >> 5);
    if (node >= nend) return;
    const int lane = threadIdx.x & 31;
    const int slot = lane >> 3;   // 0..3 : edge slot
    const int q = lane & 7;       // 16-byte chunk (cols 8q..8q+7)
    const int beg = off[node];
    const int d = degi[node];
    const int* cp = csr + beg;
    float2 a0 = {0.f, 0.f}, a1 = {0.f, 0.f}, a2 = {0.f, 0.f}, a3 = {0.f, 0.f};
    int i = slot;
    for (; i + 12 < d; i += 16) {   // 4 edges in flight per slot
        int s0 = __ldg(&cp[i]);
        int s1 = __ldg(&cp[i + 4]);
        int s2 = __ldg(&cp[i + 8]);
        int s3 = __ldg(&cp[i + 12]);
        uint4 v0 = __ldg(&hh[s0 * 8 + q]);
        uint4 v1 = __ldg(&hh[s1 * 8 + q]);
        uint4 v2 = __ldg(&hh[s2 * 8 + q]);
        uint4 v3 = __ldg(&hh[s3 * 8 + q]);
        acc_u4(v0, a0, a1, a2, a3);
        acc_u4(v1, a0, a1, a2, a3);
        acc_u4(v2, a0, a1, a2, a3);
        acc_u4(v3, a0, a1, a2, a3);
    }
    for (; i < d; i += 4) {
        int s = __ldg(&cp[i]);
        uint4 v = __ldg(&hh[s * 8 + q]);
        acc_u4(v, a0, a1, a2, a3);
    }
    a0.x += __shfl_xor_sync(0xffffffffu, a0.x, 8);  a0.x += __shfl_xor_sync(0xffffffffu, a0.x, 16);
    a0.y += __shfl_xor_sync(0xffffffffu, a0.y, 8);  a0.y += __shfl_xor_sync(0xffffffffu, a0.y, 16);
    a1.x += __shfl_xor_sync(0xffffffffu, a1.x, 8);  a1.x += __shfl_xor_sync(0xffffffffu, a1.x, 16);
    a1.y += __shfl_xor_sync(0xffffffffu, a1.y, 8);  a1.y += __shfl_xor_sync(0xffffffffu, a1.y, 16);
    a2.x += __shfl_xor_sync(0xffffffffu, a2.x, 8);  a2.x += __shfl_xor_sync(0xffffffffu, a2.x, 16);
    a2.y += __shfl_xor_sync(0xffffffffu, a2.y, 8);  a2.y += __shfl_xor_sync(0xffffffffu, a2.y, 16);
    a3.x += __shfl_xor_sync(0xffffffffu, a3.x, 8);  a3.x += __shfl_xor_sync(0xffffffffu, a3.x, 16);
    a3.y += __shfl_xor_sync(0xffffffffu, a3.y, 8);  a3.y += __shfl_xor_sync(0xffffffffu, a3.y, 16);
    if (slot == 0) {
        float inv = 1.0f / fmaxf((float)d, 1.0f);
        uint4 o;
        o.x = h2u(__floats2half2_rn(a0.x * inv, a0.y * inv));
        o.y = h2u(__floats2half2_rn(a1.x * inv, a1.y * inv));
        o.z = h2u(__floats2half2_rn(a2.x * inv, a2.y * inv));
        o.w = h2u(__floats2half2_rn(a3.x * inv, a3.y * inv));
        ag[(size_t)node * 8 + q] = o;
    }
}

// ======= proj via tensor cores, in-kernel vectorized hi/lo fp16 split =======
#define PSTRIDE 184       // halves; 368 B rows (= 23*16, uint4-aligned); ldmatrix conflict-free
#define PROJ_SMEM_BYTES (4 * 64 * PSTRIDE * 2)   // Whi, Wlo, Ahi, Alo

__global__ __launch_bounds__(256) void proj_mma(
    const float* __restrict__ x,
    const float* __restrict__ Wp, const float* __restrict__ bp, uint4* __restrict__ hh)
{
    extern __shared__ char smraw[];
    __half* Whi = reinterpret_cast<__half*>(smraw);
    __half* Wlo = Whi + 64 * PSTRIDE;
    __half* Ahi = Wlo + 64 * PSTRIDE;
    __half* Alo = Ahi + 64 * PSTRIDE;
    char* AhiB = reinterpret_cast<char*>(Ahi);
    char* AloB = reinterpret_cast<char*>(Alo);
    const int t = threadIdx.x;

    for (int i = t; i < 64 * PK; i += 256) {
        int n = i / PK, k = i - n * PK;
        float v = (k < IND) ? Wp[k * 64 + n] : 0.0f;
        __half h = __float2half_rn(v);
        Whi[n * PSTRIDE + k] = h;
        Wlo[n * PSTRIDE + k] = __float2half_rn(v - __half2float(h));
    }

    const int w = t >> 5, lane = t & 31;
    const int wr = w & 3;
    const int ch = w >> 2;
    const int gid = lane >> 2, tig = lane & 3;
    const unsigned ahi_base = (unsigned)__cvta_generic_to_shared(Ahi);
    const unsigned alo_base = (unsigned)__cvta_generic_to_shared(Alo);
    const unsigned lm_off = (unsigned)((wr * 16 + ((lane >> 3) & 1) * 8 + (lane & 7)) * (PSTRIDE * 2))
                          + (unsigned)(((lane >> 4) * 8) * 2);
    float bias01[4], bias23[4];
    #pragma unroll
    for (int nt = 0; nt < 4; nt++) {
        int col = ch * 32 + nt * 8 + tig * 2;
        bias01[nt] = bp[col];
        bias23[nt] = bp[col + 1];
    }

    for (int tile = blockIdx.x; tile < NTILES; tile += gridDim.x) {
        const int n0 = tile * 64;
        __syncthreads();
        for (int i = t; i < 64 * NG; i += 256) {
            int node = i / NG;
            int g = i - node * NG;
            int col0 = g * 8;
            const float* xr = x + (size_t)(n0 + node) * IND;
            __half hs[8], ls[8];
            #pragma unroll
            for (int j = 0; j < 8; j++) {
                int col = col0 + j;
                float v = (col < IND) ? __ldg(&xr[col]) : 0.0f;
                __half h = __float2half_rn(v);
                hs[j] = h;
                ls[j] = __float2half_rn(v - __half2float(h));
            }
            int boff = node * (PSTRIDE * 2) + g * 16;
            *reinterpret_cast<uint4*>(AhiB + boff) = *reinterpret_cast<uint4*>(hs);
            *reinterpret_cast<uint4*>(AloB + boff) = *reinterpret_cast<uint4*>(ls);
        }
        __syncthreads();
        float acc[4][4];
        #pragma unroll
        for (int nt = 0; nt < 4; nt++) {
            acc[nt][0] = bias01[nt]; acc[nt][1] = bias23[nt];
            acc[nt][2] = bias01[nt]; acc[nt][3] = bias23[nt];
        }
        #pragma unroll
        for (int ks = 0; ks < PK / 16; ks++) {   // 11
            unsigned h0r, h1r, h2r, h3r, l0r, l1r, l2r, l3r;
            unsigned ah = ahi_base + lm_off + (unsigned)(ks * 16 * 2);
            unsigned al = alo_base + lm_off + (unsigned)(ks * 16 * 2);
            asm volatile("ldmatrix.sync.aligned.m8n8.x4.shared.b16 {%0,%1,%2,%3}, [%4];"
                         : "=r"(h0r), "=r"(h1r), "=r"(h2r), "=r"(h3r) : "r"(ah));
            asm volatile("ldmatrix.sync.aligned.m8n8.x4.shared.b16 {%0,%1,%2,%3}, [%4];"
                         : "=r"(l0r), "=r"(l1r), "=r"(l2r), "=r"(l3r) : "r"(al));
            #pragma unroll
            for (int nt = 0; nt < 4; nt++) {
                int n = ch * 32 + nt * 8 + gid;
                int k = ks * 16 + tig * 2;
                unsigned bh0 = *reinterpret_cast<const unsigned*>(&Whi[n * PSTRIDE + k]);
                unsigned bh1 = *reinterpret_cast<const unsigned*>(&Whi[n * PSTRIDE + k + 8]);
                unsigned bl0 = *reinterpret_cast<const unsigned*>(&Wlo[n * PSTRIDE + k]);
                unsigned bl1 = *reinterpret_cast<const unsigned*>(&Wlo[n * PSTRIDE + k + 8]);
                asm volatile(
                    "mma.sync.aligned.m16n8k16.row.col.f32.f16.f16.f32 "
                    "{%0,%1,%2,%3}, {%4,%5,%6,%7}, {%8,%9}, {%0,%1,%2,%3};"
                    : "+f"(acc[nt][0]), "+f"(acc[nt][1]), "+f"(acc[nt][2]), "+f"(acc[nt][3])
                    : "r"(h0r), "r"(h1r), "r"(h2r), "r"(h3r), "r"(bh0), "r"(bh1));
                asm volatile(
                    "mma.sync.aligned.m16n8k16.row.col.f32.f16.f16.f32 "
                    "{%0,%1,%2,%3}, {%4,%5,%6,%7}, {%8,%9}, {%0,%1,%2,%3};"
                    : "+f"(acc[nt][0]), "+f"(acc[nt][1]), "+f"(acc[nt][2]), "+f"(acc[nt][3])
                    : "r"(l0r), "r"(l1r), "r"(l2r), "r"(l3r), "r"(bh0), "r"(bh1));
                asm volatile(
                    "mma.sync.aligned.m16n8k16.row.col.f32.f16.f16.f32 "
                    "{%0,%1,%2,%3}, {%4,%5,%6,%7}, {%8,%9}, {%0,%1,%2,%3};"
                    : "+f"(acc[nt][0]), "+f"(acc[nt][1]), "+f"(acc[nt][2]), "+f"(acc[nt][3])
                    : "r"(h0r), "r"(h1r), "r"(h2r), "r"(h3r), "r"(bl0), "r"(bl1));
            }
        }
        #pragma unroll
        for (int nt = 0; nt < 4; nt++) {
            int col = ch * 32 + nt * 8 + tig * 2;
            int r0 = n0 + wr * 16 + gid;
            unsigned u0 = h2u(__floats2half2_rn(fmaxf(acc[nt][0], 0.f), fmaxf(acc[nt][1], 0.f)));
            unsigned u1 = h2u(__floats2half2_rn(fmaxf(acc[nt][2], 0.f), fmaxf(acc[nt][3], 0.f)));
            reinterpret_cast<unsigned*>(hh)[(size_t)r0 * 32 + (col >> 1)] = u0;
            reinterpret_cast<unsigned*>(hh)[(size_t)(r0 + 8) * 32 + (col >> 1)] = u1;
        }
    }
}

// ====== SAGE via tensor cores over tile range [tbeg, tend) ======
#define WT_STRIDE 136
#define AS_STRIDE_H 136
#define SAGE_SMEM_BYTES (64 * WT_STRIDE * 2 + 64 * AS_STRIDE_H * 2 + 2 * 64 * 4)

template<bool FINAL>
__global__ __launch_bounds__(256) void sage_mma(
    const uint4* __restrict__ hh,      // self rows fp16
    const uint4* __restrict__ ag,      // aggr rows fp16
    const float* __restrict__ Wl, const float* __restrict__ bl,
    const float* __restrict__ Wr,
    unsigned* __restrict__ hh_out,     // non-final: fp16 output rows
    float* __restrict__ out,           // final: [Nn]
    const float* __restrict__ Wc, const float* __restrict__ bc,
    int tbeg, int tend)
{
    extern __shared__ char smraw[];
    __half* Wt = reinterpret_cast<__half*>(smraw);
    __half* As = reinterpret_cast<__half*>(smraw + 64 * WT_STRIDE * 2);
    float* partial = reinterpret_cast<float*>(smraw + 64 * WT_STRIDE * 2 + 64 * AS_STRIDE_H * 2);
    const int t = threadIdx.x;
    for (int i = t; i < 64 * 128; i += 256) {
        int n = i >> 7, k = i & 127;
        float v = (k < 64) ? Wl[k * 64 + n] : Wr[(k - 64) * 64 + n];
        Wt[n * WT_STRIDE + k] = __float2half(v);
    }
    const int w = t >> 5, lane = t & 31;
    const int wr = w & 3;
    const int ch = w >> 2;
    const int gid = lane >> 2, tig = lane & 3;
    const unsigned as_base = (unsigned)__cvta_generic_to_shared(As);
    const unsigned lm_base = as_base
        + (unsigned)((wr * 16 + ((lane >> 3) & 1) * 8 + (lane & 7)) * (AS_STRIDE_H * 2))
        + (unsigned)(((lane >> 4) * 8) * 2);
    float bias01[4], bias23[4];
    float wc0[4], wc1[4];
    #pragma unroll
    for (int nt = 0; nt < 4; nt++) {
        int col = ch * 32 + nt * 8 + tig * 2;
        bias01[nt] = bl[col];
        bias23[nt] = bl[col + 1];
        if (FINAL) { wc0[nt] = Wc[col]; wc1[nt] = Wc[col + 1]; }
    }
    float bc0 = FINAL ? bc[0] : 0.f;

    for (int tile = tbeg + blockIdx.x; tile < tend; tile += gridDim.x) {
        const int n0 = tile * 64;
        __syncthreads();
        for (int i = t; i < 64 * 16; i += 256) {
            int node = i >> 4, p = i & 15;
            uint4 v = (p < 8) ? ag[(size_t)(n0 + node) * 8 + p]
                              : hh[(size_t)(n0 + node) * 8 + (p - 8)];
            *reinterpret_cast<uint4*>(reinterpret_cast<char*>(As) + node * (AS_STRIDE_H * 2) + p * 16) = v;
        }
        __syncthreads();
        float acc[4][4];
        #pragma unroll
        for (int nt = 0; nt < 4; nt++) {
            acc[nt][0] = bias01[nt]; acc[nt][1] = bias23[nt];
            acc[nt][2] = bias01[nt]; acc[nt][3] = bias23[nt];
        }
        #pragma unroll
        for (int ks = 0; ks < 8; ks++) {
            unsigned a0, a1, a2, a3;
            unsigned addr = lm_base + (unsigned)(ks * 16 * 2);
            asm volatile("ldmatrix.sync.aligned.m8n8.x4.shared.b16 {%0,%1,%2,%3}, [%4];"
                         : "=r"(a0), "=r"(a1), "=r"(a2), "=r"(a3) : "r"(addr));
            #pragma unroll
            for (int nt = 0; nt < 4; nt++) {
                int n = ch * 32 + nt * 8 + gid;
                int k = ks * 16 + tig * 2;
                unsigned b0 = *reinterpret_cast<const unsigned*>(&Wt[n * WT_STRIDE + k]);
                unsigned b1 = *reinterpret_cast<const unsigned*>(&Wt[n * WT_STRIDE + k + 8]);
                asm volatile(
                    "mma.sync.aligned.m16n8k16.row.col.f32.f16.f16.f32 "
                    "{%0,%1,%2,%3}, {%4,%5,%6,%7}, {%8,%9}, {%0,%1,%2,%3};"
                    : "+f"(acc[nt][0]), "+f"(acc[nt][1]), "+f"(acc[nt][2]), "+f"(acc[nt][3])
                    : "r"(a0), "r"(a1), "r"(a2), "r"(a3), "r"(b0), "r"(b1));
            }
        }
        if (FINAL) {
            float s0 = 0.f, s1 = 0.f;
            #pragma unroll
            for (int nt = 0; nt < 4; nt++) {
                s0 = fmaf(fmaxf(acc[nt][0], 0.f), wc0[nt], s0);
                s0 = fmaf(fmaxf(acc[nt][1], 0.f), wc1[nt], s0);
                s1 = fmaf(fmaxf(acc[nt][2], 0.f), wc0[nt], s1);
                s1 = fmaf(fmaxf(acc[nt][3], 0.f), wc1[nt], s1);
            }
            s0 += __shfl_xor_sync(0xffffffffu, s0, 1);
            s0 += __shfl_xor_sync(0xffffffffu, s0, 2);
            s1 += __shfl_xor_sync(0xffffffffu, s1, 1);
            s1 += __shfl_xor_sync(0xffffffffu, s1, 2);
            if (tig == 0) {
                partial[ch * 64 + wr * 16 + gid] = s0;
                partial[ch * 64 + wr * 16 + gid + 8] = s1;
            }
            __syncthreads();
            if (t < 64) out[n0 + t] = partial[t] + partial[64 + t] + bc0;
        } else {
            #pragma unroll
            for (int nt = 0; nt < 4; nt++) {
                int col = ch * 32 + nt * 8 + tig * 2;
                int r0 = n0 + wr * 16 + gid;
                unsigned u0 = h2u(__floats2half2_rn(fmaxf(acc[nt][0], 0.f), fmaxf(acc[nt][1], 0.f)));
                unsigned u1 = h2u(__floats2half2_rn(fmaxf(acc[nt][2], 0.f), fmaxf(acc[nt][3], 0.f)));
                hh_out[(size_t)r0 * 32 + (col >> 1)] = u0;
                hh_out[(size_t)(r0 + 8) * 32 + (col >> 1)] = u1;
            }
        }
    }
}

extern "C" void kernel_launch(void* const* d_in, const int* in_sizes, int n_in,
                              void* d_out, int out_size)
{
    const float* x   = (const float*)d_in[0];
    const int*   ei  = (const int*)d_in[1];
    const float* Wp  = (const float*)d_in[2];
    const float* bp  = (const float*)d_in[3];
    const float* W1l = (const float*)d_in[4];
    const float* b1l = (const float*)d_in[5];
    const float* W1r = (const float*)d_in[6];
    const float* W2l = (const float*)d_in[7];
    const float* b2l = (const float*)d_in[8];
    const float* W2r = (const float*)d_in[9];
    const float* Wc  = (const float*)d_in[10];
    const float* bc  = (const float*)d_in[11];
    float* out = (float*)d_out;

    const int* src = ei;
    const int* dst = ei + Ee;

    uint4 *hh0, *hh1, *ag;
    int *degi, *off, *cur, *csr, *bsum, *bscan;
    cudaGetSymbolAddress((void**)&hh0, g_hh0);
    cudaGetSymbolAddress((void**)&hh1, g_hh1);
    cudaGetSymbolAddress((void**)&ag, g_ag);
    cudaGetSymbolAddress((void**)&degi, g_degi);
    cudaGetSymbolAddress((void**)&off, g_off);
    cudaGetSymbolAddress((void**)&cur, g_cur);
    cudaGetSymbolAddress((void**)&csr, g_csr);
    cudaGetSymbolAddress((void**)&bsum, g_bsum);
    cudaGetSymbolAddress((void**)&bscan, g_bscan);

    static cudaStream_t s2 = nullptr;
    static cudaEvent_t evFork = nullptr, evJoin = nullptr;
    static cudaEvent_t evG[2] = {nullptr, nullptr};   // gather chunk-0 done (per layer)
    static cudaEvent_t evS[2] = {nullptr, nullptr};   // sage chunk-0 done (per layer)
    if (!s2) {
        cudaStreamCreateWithFlags(&s2, cudaStreamNonBlocking);
        cudaEventCreateWithFlags(&evFork, cudaEventDisableTiming);
        cudaEventCreateWithFlags(&evJoin, cudaEventDisableTiming);
        for (int i = 0; i < 2; i++) {
            cudaEventCreateWithFlags(&evG[i], cudaEventDisableTiming);
            cudaEventCreateWithFlags(&evS[i], cudaEventDisableTiming);
        }
        cudaFuncSetAttribute(proj_mma, cudaFuncAttributeMaxDynamicSharedMemorySize, PROJ_SMEM_BYTES);
    }

    const int gblocks0 = (NSPLIT * 32) / 256;                 // chunk-0 gather blocks
    const int gblocks1 = ((Nn - NSPLIT) * 32 + 255) / 256;    // chunk-1 gather blocks

    // ---- fork: CSR build on side stream, proj on main stream ----
    cudaEventRecord(evFork, 0);
    cudaStreamWaitEvent(s2, evFork, 0);

    cudaMemsetAsync(degi, 0, Nn * sizeof(int), s2);
    deg_kernel<<<(Ee / 4 + 255) / 256, 256, 0, s2>>>(dst, degi);
    scan1<<<NB1K, 256, 0, s2>>>(degi, bsum);
    scan2<<<1, 256, 0, s2>>>(bsum, bscan);
    scan3<<<NB1K, 256, 0, s2>>>(degi, bscan, off, cur);
    place_kernel<<<(Ee / 4 + 255) / 256, 256, 0, s2>>>(src, dst, cur, csr);
    cudaEventRecord(evJoin, s2);

    proj_mma<<<296, 256, PROJ_SMEM_BYTES>>>(x, Wp, bp, hh0);

    // ---- join ----
    cudaStreamWaitEvent(0, evJoin, 0);

    // ==== layer 1 (chunk-pipelined) ====
    gather_mean_h<<<gblocks0, 256>>>(csr, off, degi, hh0, ag, 0, NSPLIT);
    cudaEventRecord(evG[0], 0);
    cudaStreamWaitEvent(s2, evG[0], 0);
    sage_mma<false><<<444, 256, SAGE_SMEM_BYTES, s2>>>(hh0, ag, W1l, b1l, W1r,
                                                       (unsigned*)hh1, nullptr, nullptr, nullptr,
                                                       0, TSPLIT);
    cudaEventRecord(evS[0], s2);
    gather_mean_h<<<gblocks1, 256>>>(csr, off, degi, hh0, ag, NSPLIT, Nn);
    sage_mma<false><<<444, 256, SAGE_SMEM_BYTES>>>(hh0, ag, W1l, b1l, W1r,
                                                   (unsigned*)hh1, nullptr, nullptr, nullptr,
                                                   TSPLIT, NTILES);
    cudaStreamWaitEvent(0, evS[0], 0);   // hh1 fully written before layer-2 gather

    // ==== layer 2 (chunk-pipelined, FINAL fuses classifier) ====
    gather_mean_h<<<gblocks0, 256>>>(csr, off, degi, hh1, ag, 0, NSPLIT);
    cudaEventRecord(evG[1], 0);
    cudaStreamWaitEvent(s2, evG[1], 0);
    sage_mma<true><<<444, 256, SAGE_SMEM_BYTES, s2>>>(hh1, ag, W2l, b2l, W2r,
                                                      nullptr, out, Wc, bc,
                                                      0, TSPLIT);
    cudaEventRecord(evS[1], s2);
    gather_mean_h<<<gblocks1, 256>>>(csr, off, degi, hh1, ag, NSPLIT, Nn);
    sage_mma<true><<<444, 256, SAGE_SMEM_BYTES>>>(hh1, ag, W2l, b2l, W2r,
                                                  nullptr, out, Wc, bc,
                                                  TSPLIT, NTILES);
    cudaStreamWaitEvent(0, evS[1], 0);   // ensure both sage chunks complete on stream 0
}

// round 17
// speedup vs baseline: 1.1034x; 1.1034x over previous
#include <cuda_runtime.h>
#include <cuda_fp16.h>

#define Nn 200000
#define Ee 3200000
#define IND 165
#define HID 64
#define NB1K 196   // ceil(Nn/1024)
#define PK 176     // K padded to 11x16
#define NG 22      // 8-col groups per padded row

// ---- scratch (no cudaMalloc allowed) ----
__device__ uint4 g_hh0[Nn * 8];   // fp16 h0 rows (64 halves = 8 uint4)
__device__ uint4 g_hh1[Nn * 8];   // fp16 h1 rows
__device__ uint4 g_ag[Nn * 8];    // fp16 aggregated-mean rows
__device__ int   g_degi[Nn];
__device__ int   g_off[Nn];
__device__ int   g_cur[Nn];
__device__ int   g_csr[Ee];
__device__ int   g_bsum[256];
__device__ int   g_bscan[256];

__device__ __forceinline__ unsigned h2u(__half2 h) {
    return *reinterpret_cast<unsigned*>(&h);
}

// =================== degree histogram (int4) ===================
__global__ __launch_bounds__(256) void deg_kernel(const int* __restrict__ dst, int* __restrict__ degi)
{
    int t = blockIdx.x * blockDim.x + threadIdx.x;
    if (t < Ee / 4) {
        int4 d4 = reinterpret_cast<const int4*>(dst)[t];
        atomicAdd(&degi[d4.x], 1);
        atomicAdd(&degi[d4.y], 1);
        atomicAdd(&degi[d4.z], 1);
        atomicAdd(&degi[d4.w], 1);
    }
}

// =================== 2-level exclusive scan ===================
__global__ __launch_bounds__(256) void scan1(const int* __restrict__ degi, int* __restrict__ bsum)
{
    __shared__ int s[256];
    int base = blockIdx.x * 1024 + threadIdx.x * 4;
    int sum = 0;
    #pragma unroll
    for (int i = 0; i < 4; i++) { int n = base + i; if (n < Nn) sum += degi[n]; }
    s[threadIdx.x] = sum; __syncthreads();
    for (int o = 128; o; o >>= 1) {
        if (threadIdx.x < o) s[threadIdx.x] += s[threadIdx.x + o];
        __syncthreads();
    }
    if (threadIdx.x == 0) bsum[blockIdx.x] = s[0];
}

__global__ __launch_bounds__(256) void scan2(const int* __restrict__ bsum, int* __restrict__ bscan)
{
    __shared__ int s[256];
    int v = (threadIdx.x < NB1K) ? bsum[threadIdx.x] : 0;
    s[threadIdx.x] = v; __syncthreads();
    for (int o = 1; o < 256; o <<= 1) {
        int t = (threadIdx.x >= o) ? s[threadIdx.x - o] : 0;
        __syncthreads();
        s[threadIdx.x] += t;
        __syncthreads();
    }
    if (threadIdx.x < NB1K) bscan[threadIdx.x] = s[threadIdx.x] - v;  // exclusive
}

__global__ __launch_bounds__(256) void scan3(const int* __restrict__ degi, const int* __restrict__ bscan,
                                             int* __restrict__ off, int* __restrict__ cur)
{
    __shared__ int s[256];
    int tid = threadIdx.x;
    int base = blockIdx.x * 1024 + tid * 4;
    int d[4]; int sum = 0;
    #pragma unroll
    for (int i = 0; i < 4; i++) { int n = base + i; d[i] = (n < Nn) ? degi[n] : 0; sum += d[i]; }
    s[tid] = sum; __syncthreads();
    for (int o = 1; o < 256; o <<= 1) {
        int t = (tid >= o) ? s[tid - o] : 0;
        __syncthreads();
        s[tid] += t;
        __syncthreads();
    }
    int ex = s[tid] - sum + bscan[blockIdx.x];
    #pragma unroll
    for (int i = 0; i < 4; i++) {
        int n = base + i;
        if (n < Nn) { off[n] = ex; cur[n] = ex; ex += d[i]; }
    }
}

__global__ __launch_bounds__(256) void place_kernel(const int* __restrict__ src, const int* __restrict__ dst,
                                                    int* __restrict__ cur, int* __restrict__ csr)
{
    int t = blockIdx.x * blockDim.x + threadIdx.x;
    if (t < Ee / 4) {
        int4 s4 = reinterpret_cast<const int4*>(src)[t];
        int4 d4 = reinterpret_cast<const int4*>(dst)[t];
        int p;
        p = atomicAdd(&cur[d4.x], 1); csr[p] = s4.x;
        p = atomicAdd(&cur[d4.y], 1); csr[p] = s4.y;
        p = atomicAdd(&cur[d4.z], 1); csr[p] = s4.z;
        p = atomicAdd(&cur[d4.w], 1); csr[p] = s4.w;
    }
}

// ======== gather-mean fp16->fp32->fp16 (warp per node, 4 edge-slots x 8 lanes) ========
__device__ __forceinline__ void acc_u4(const uint4& v, float2& a0, float2& a1, float2& a2, float2& a3)
{
    float2 f;
    f = __half22float2(*reinterpret_cast<const __half2*>(&v.x)); a0.x += f.x; a0.y += f.y;
    f = __half22float2(*reinterpret_cast<const __half2*>(&v.y)); a1.x += f.x; a1.y += f.y;
    f = __half22float2(*reinterpret_cast<const __half2*>(&v.z)); a2.x += f.x; a2.y += f.y;
    f = __half22float2(*reinterpret_cast<const __half2*>(&v.w)); a3.x += f.x; a3.y += f.y;
}

__global__ __launch_bounds__(256) void gather_mean_h(
    const int* __restrict__ csr, const int* __restrict__ off, const int* __restrict__ degi,
    const uint4* __restrict__ hh, uint4* __restrict__ ag)
{
    int node = (int)((blockIdx.x * (unsigned)blockDim.x + threadIdx.x) >> 5);
    if (node >= Nn) return;
    const int lane = threadIdx.x & 31;
    const int slot = lane >> 3;   // 0..3 : edge slot
    const int q = lane & 7;       // 16-byte chunk (cols 8q..8q+7)
    const int beg = off[node];
    const int d = degi[node];
    const int* cp = csr + beg;
    float2 a0 = {0.f, 0.f}, a1 = {0.f, 0.f}, a2 = {0.f, 0.f}, a3 = {0.f, 0.f};
    int i = slot;
    for (; i + 12 < d; i += 16) {   // 4 edges in flight per slot
        int s0 = __ldg(&cp[i]);
        int s1 = __ldg(&cp[i + 4]);
        int s2 = __ldg(&cp[i + 8]);
        int s3 = __ldg(&cp[i + 12]);
        uint4 v0 = __ldg(&hh[s0 * 8 + q]);
        uint4 v1 = __ldg(&hh[s1 * 8 + q]);
        uint4 v2 = __ldg(&hh[s2 * 8 + q]);
        uint4 v3 = __ldg(&hh[s3 * 8 + q]);
        acc_u4(v0, a0, a1, a2, a3);
        acc_u4(v1, a0, a1, a2, a3);
        acc_u4(v2, a0, a1, a2, a3);
        acc_u4(v3, a0, a1, a2, a3);
    }
    // predicated batched tail: at most 3 edges left per slot (i, i+4, i+8);
    // issue all index loads, then all row loads concurrently. Predicated-off
    // contributions are exact +0.0 -> bit-identical result.
    {
        const bool p0 = (i < d), p1 = (i + 4 < d), p2 = (i + 8 < d);
        const uint4 z = make_uint4(0u, 0u, 0u, 0u);
        int s0 = p0 ? __ldg(&cp[i]) : 0;
        int s1 = p1 ? __ldg(&cp[i + 4]) : 0;
        int s2 = p2 ? __ldg(&cp[i + 8]) : 0;
        uint4 v0 = p0 ? __ldg(&hh[s0 * 8 + q]) : z;
        uint4 v1 = p1 ? __ldg(&hh[s1 * 8 + q]) : z;
        uint4 v2 = p2 ? __ldg(&hh[s2 * 8 + q]) : z;
        acc_u4(v0, a0, a1, a2, a3);
        acc_u4(v1, a0, a1, a2, a3);
        acc_u4(v2, a0, a1, a2, a3);
    }
    a0.x += __shfl_xor_sync(0xffffffffu, a0.x, 8);  a0.x += __shfl_xor_sync(0xffffffffu, a0.x, 16);
    a0.y += __shfl_xor_sync(0xffffffffu, a0.y, 8);  a0.y += __shfl_xor_sync(0xffffffffu, a0.y, 16);
    a1.x += __shfl_xor_sync(0xffffffffu, a1.x, 8);  a1.x += __shfl_xor_sync(0xffffffffu, a1.x, 16);
    a1.y += __shfl_xor_sync(0xffffffffu, a1.y, 8);  a1.y += __shfl_xor_sync(0xffffffffu, a1.y, 16);
    a2.x += __shfl_xor_sync(0xffffffffu, a2.x, 8);  a2.x += __shfl_xor_sync(0xffffffffu, a2.x, 16);
    a2.y += __shfl_xor_sync(0xffffffffu, a2.y, 8);  a2.y += __shfl_xor_sync(0xffffffffu, a2.y, 16);
    a3.x += __shfl_xor_sync(0xffffffffu, a3.x, 8);  a3.x += __shfl_xor_sync(0xffffffffu, a3.x, 16);
    a3.y += __shfl_xor_sync(0xffffffffu, a3.y, 8);  a3.y += __shfl_xor_sync(0xffffffffu, a3.y, 16);
    if (slot == 0) {
        float inv = 1.0f / fmaxf((float)d, 1.0f);
        uint4 o;
        o.x = h2u(__floats2half2_rn(a0.x * inv, a0.y * inv));
        o.y = h2u(__floats2half2_rn(a1.x * inv, a1.y * inv));
        o.z = h2u(__floats2half2_rn(a2.x * inv, a2.y * inv));
        o.w = h2u(__floats2half2_rn(a3.x * inv, a3.y * inv));
        ag[(size_t)node * 8 + q] = o;
    }
}

// ======= proj via tensor cores, in-kernel vectorized hi/lo fp16 split =======
// acc = x_hi*W_hi + x_lo*W_hi + x_hi*W_lo  (lo*lo dropped, ~1e-7)
#define PSTRIDE 184       // halves; 368 B rows (= 23*16, uint4-aligned); ldmatrix conflict-free
#define PROJ_SMEM_BYTES (4 * 64 * PSTRIDE * 2)   // Whi, Wlo, Ahi, Alo

__global__ __launch_bounds__(256) void proj_mma(
    const float* __restrict__ x,
    const float* __restrict__ Wp, const float* __restrict__ bp, uint4* __restrict__ hh)
{
    extern __shared__ char smraw[];
    __half* Whi = reinterpret_cast<__half*>(smraw);
    __half* Wlo = Whi + 64 * PSTRIDE;
    __half* Ahi = Wlo + 64 * PSTRIDE;
    __half* Alo = Ahi + 64 * PSTRIDE;
    char* AhiB = reinterpret_cast<char*>(Ahi);
    char* AloB = reinterpret_cast<char*>(Alo);
    const int t = threadIdx.x;

    for (int i = t; i < 64 * PK; i += 256) {
        int n = i / PK, k = i - n * PK;
        float v = (k < IND) ? Wp[k * 64 + n] : 0.0f;
        __half h = __float2half_rn(v);
        Whi[n * PSTRIDE + k] = h;
        Wlo[n * PSTRIDE + k] = __float2half_rn(v - __half2float(h));
    }

    const int w = t >> 5, lane = t & 31;
    const int wr = w & 3;        // 16-row block
    const int ch = w >> 2;       // 32-col half
    const int gid = lane >> 2, tig = lane & 3;
    const unsigned ahi_base = (unsigned)__cvta_generic_to_shared(Ahi);
    const unsigned alo_base = (unsigned)__cvta_generic_to_shared(Alo);
    const unsigned lm_off = (unsigned)((wr * 16 + ((lane >> 3) & 1) * 8 + (lane & 7)) * (PSTRIDE * 2))
                          + (unsigned)(((lane >> 4) * 8) * 2);
    float bias01[4], bias23[4];
    #pragma unroll
    for (int nt = 0; nt < 4; nt++) {
        int col = ch * 32 + nt * 8 + tig * 2;
        bias01[nt] = bp[col];
        bias23[nt] = bp[col + 1];
    }

    const int ntiles = Nn / 64;  // 3125
    for (int tile = blockIdx.x; tile < ntiles; tile += gridDim.x) {
        const int n0 = tile * 64;
        __syncthreads();
        // fill A tiles: per (node, 8-col group): 8 predicated LDG, in-reg split, 2 uint4 STS
        for (int i = t; i < 64 * NG; i += 256) {
            int node = i / NG;
            int g = i - node * NG;
            int col0 = g * 8;
            const float* xr = x + (size_t)(n0 + node) * IND;
            __half hs[8], ls[8];
            #pragma unroll
            for (int j = 0; j < 8; j++) {
                int col = col0 + j;
                float v = (col < IND) ? __ldg(&xr[col]) : 0.0f;
                __half h = __float2half_rn(v);
                hs[j] = h;
                ls[j] = __float2half_rn(v - __half2float(h));
            }
            int boff = node * (PSTRIDE * 2) + g * 16;
            *reinterpret_cast<uint4*>(AhiB + boff) = *reinterpret_cast<uint4*>(hs);
            *reinterpret_cast<uint4*>(AloB + boff) = *reinterpret_cast<uint4*>(ls);
        }
        __syncthreads();
        float acc[4][4];
        #pragma unroll
        for (int nt = 0; nt < 4; nt++) {
            acc[nt][0] = bias01[nt]; acc[nt][1] = bias23[nt];
            acc[nt][2] = bias01[nt]; acc[nt][3] = bias23[nt];
        }
        #pragma unroll
        for (int ks = 0; ks < PK / 16; ks++) {   // 11
            unsigned h0r, h1r, h2r, h3r, l0r, l1r, l2r, l3r;
            unsigned ah = ahi_base + lm_off + (unsigned)(ks * 16 * 2);
            unsigned al = alo_base + lm_off + (unsigned)(ks * 16 * 2);
            asm volatile("ldmatrix.sync.aligned.m8n8.x4.shared.b16 {%0,%1,%2,%3}, [%4];"
                         : "=r"(h0r), "=r"(h1r), "=r"(h2r), "=r"(h3r) : "r"(ah));
            asm volatile("ldmatrix.sync.aligned.m8n8.x4.shared.b16 {%0,%1,%2,%3}, [%4];"
                         : "=r"(l0r), "=r"(l1r), "=r"(l2r), "=r"(l3r) : "r"(al));
            #pragma unroll
            for (int nt = 0; nt < 4; nt++) {
                int n = ch * 32 + nt * 8 + gid;
                int k = ks * 16 + tig * 2;
                unsigned bh0 = *reinterpret_cast<const unsigned*>(&Whi[n * PSTRIDE + k]);
                unsigned bh1 = *reinterpret_cast<const unsigned*>(&Whi[n * PSTRIDE + k + 8]);
                unsigned bl0 = *reinterpret_cast<const unsigned*>(&Wlo[n * PSTRIDE + k]);
                unsigned bl1 = *reinterpret_cast<const unsigned*>(&Wlo[n * PSTRIDE + k + 8]);
                asm volatile(
                    "mma.sync.aligned.m16n8k16.row.col.f32.f16.f16.f32 "
                    "{%0,%1,%2,%3}, {%4,%5,%6,%7}, {%8,%9}, {%0,%1,%2,%3};"
                    : "+f"(acc[nt][0]), "+f"(acc[nt][1]), "+f"(acc[nt][2]), "+f"(acc[nt][3])
                    : "r"(h0r), "r"(h1r), "r"(h2r), "r"(h3r), "r"(bh0), "r"(bh1));
                asm volatile(
                    "mma.sync.aligned.m16n8k16.row.col.f32.f16.f16.f32 "
                    "{%0,%1,%2,%3}, {%4,%5,%6,%7}, {%8,%9}, {%0,%1,%2,%3};"
                    : "+f"(acc[nt][0]), "+f"(acc[nt][1]), "+f"(acc[nt][2]), "+f"(acc[nt][3])
                    : "r"(l0r), "r"(l1r), "r"(l2r), "r"(l3r), "r"(bh0), "r"(bh1));
                asm volatile(
                    "mma.sync.aligned.m16n8k16.row.col.f32.f16.f16.f32 "
                    "{%0,%1,%2,%3}, {%4,%5,%6,%7}, {%8,%9}, {%0,%1,%2,%3};"
                    : "+f"(acc[nt][0]), "+f"(acc[nt][1]), "+f"(acc[nt][2]), "+f"(acc[nt][3])
                    : "r"(h0r), "r"(h1r), "r"(h2r), "r"(h3r), "r"(bl0), "r"(bl1));
            }
        }
        #pragma unroll
        for (int nt = 0; nt < 4; nt++) {
            int col = ch * 32 + nt * 8 + tig * 2;
            int r0 = n0 + wr * 16 + gid;
            unsigned u0 = h2u(__floats2half2_rn(fmaxf(acc[nt][0], 0.f), fmaxf(acc[nt][1], 0.f)));
            unsigned u1 = h2u(__floats2half2_rn(fmaxf(acc[nt][2], 0.f), fmaxf(acc[nt][3], 0.f)));
            reinterpret_cast<unsigned*>(hh)[(size_t)r0 * 32 + (col >> 1)] = u0;
            reinterpret_cast<unsigned*>(hh)[(size_t)(r0 + 8) * 32 + (col >> 1)] = u1;
        }
    }
}

// ====== SAGE via tensor cores: out = relu([ag | hh] @ [Wl ; Wr] + bl) ======
#define WT_STRIDE 136
#define AS_STRIDE_H 136
#define SAGE_SMEM_BYTES (64 * WT_STRIDE * 2 + 64 * AS_STRIDE_H * 2 + 2 * 64 * 4)

template<bool FINAL>
__global__ __launch_bounds__(256) void sage_mma(
    const uint4* __restrict__ hh,      // self rows fp16
    const uint4* __restrict__ ag,      // aggr rows fp16
    const float* __restrict__ Wl, const float* __restrict__ bl,
    const float* __restrict__ Wr,
    unsigned* __restrict__ hh_out,     // non-final: fp16 output rows
    float* __restrict__ out,           // final: [Nn]
    const float* __restrict__ Wc, const float* __restrict__ bc)
{
    extern __shared__ char smraw[];
    __half* Wt = reinterpret_cast<__half*>(smraw);
    __half* As = reinterpret_cast<__half*>(smraw + 64 * WT_STRIDE * 2);
    float* partial = reinterpret_cast<float*>(smraw + 64 * WT_STRIDE * 2 + 64 * AS_STRIDE_H * 2);
    const int t = threadIdx.x;
    for (int i = t; i < 64 * 128; i += 256) {
        int n = i >> 7, k = i & 127;
        float v = (k < 64) ? Wl[k * 64 + n] : Wr[(k - 64) * 64 + n];
        Wt[n * WT_STRIDE + k] = __float2half(v);
    }
    const int w = t >> 5, lane = t & 31;
    const int wr = w & 3;
    const int ch = w >> 2;
    const int gid = lane >> 2, tig = lane & 3;
    const unsigned as_base = (unsigned)__cvta_generic_to_shared(As);
    const unsigned lm_base = as_base
        + (unsigned)((wr * 16 + ((lane >> 3) & 1) * 8 + (lane & 7)) * (AS_STRIDE_H * 2))
        + (unsigned)(((lane >> 4) * 8) * 2);
    float bias01[4], bias23[4];
    float wc0[4], wc1[4];
    #pragma unroll
    for (int nt = 0; nt < 4; nt++) {
        int col = ch * 32 + nt * 8 + tig * 2;
        bias01[nt] = bl[col];
        bias23[nt] = bl[col + 1];
        if (FINAL) { wc0[nt] = Wc[col]; wc1[nt] = Wc[col + 1]; }
    }
    float bc0 = FINAL ? bc[0] : 0.f;

    const int ntiles = Nn / 64;  // 3125
    for (int tile = blockIdx.x; tile < ntiles; tile += gridDim.x) {
        const int n0 = tile * 64;
        __syncthreads();
        for (int i = t; i < 64 * 16; i += 256) {
            int node = i >> 4, p = i & 15;
            uint4 v = (p < 8) ? ag[(size_t)(n0 + node) * 8 + p]
                              : hh[(size_t)(n0 + node) * 8 + (p - 8)];
            *reinterpret_cast<uint4*>(reinterpret_cast<char*>(As) + node * (AS_STRIDE_H * 2) + p * 16) = v;
        }
        __syncthreads();
        float acc[4][4];
        #pragma unroll
        for (int nt = 0; nt < 4; nt++) {
            acc[nt][0] = bias01[nt]; acc[nt][1] = bias23[nt];
            acc[nt][2] = bias01[nt]; acc[nt][3] = bias23[nt];
        }
        #pragma unroll
        for (int ks = 0; ks < 8; ks++) {
            unsigned a0, a1, a2, a3;
            unsigned addr = lm_base + (unsigned)(ks * 16 * 2);
            asm volatile("ldmatrix.sync.aligned.m8n8.x4.shared.b16 {%0,%1,%2,%3}, [%4];"
                         : "=r"(a0), "=r"(a1), "=r"(a2), "=r"(a3) : "r"(addr));
            #pragma unroll
            for (int nt = 0; nt < 4; nt++) {
                int n = ch * 32 + nt * 8 + gid;
                int k = ks * 16 + tig * 2;
                unsigned b0 = *reinterpret_cast<const unsigned*>(&Wt[n * WT_STRIDE + k]);
                unsigned b1 = *reinterpret_cast<const unsigned*>(&Wt[n * WT_STRIDE + k + 8]);
                asm volatile(
                    "mma.sync.aligned.m16n8k16.row.col.f32.f16.f16.f32 "
                    "{%0,%1,%2,%3}, {%4,%5,%6,%7}, {%8,%9}, {%0,%1,%2,%3};"
                    : "+f"(acc[nt][0]), "+f"(acc[nt][1]), "+f"(acc[nt][2]), "+f"(acc[nt][3])
                    : "r"(a0), "r"(a1), "r"(a2), "r"(a3), "r"(b0), "r"(b1));
            }
        }
        if (FINAL) {
            float s0 = 0.f, s1 = 0.f;
            #pragma unroll
            for (int nt = 0; nt < 4; nt++) {
                s0 = fmaf(fmaxf(acc[nt][0], 0.f), wc0[nt], s0);
                s0 = fmaf(fmaxf(acc[nt][1], 0.f), wc1[nt], s0);
                s1 = fmaf(fmaxf(acc[nt][2], 0.f), wc0[nt], s1);
                s1 = fmaf(fmaxf(acc[nt][3], 0.f), wc1[nt], s1);
            }
            s0 += __shfl_xor_sync(0xffffffffu, s0, 1);
            s0 += __shfl_xor_sync(0xffffffffu, s0, 2);
            s1 += __shfl_xor_sync(0xffffffffu, s1, 1);
            s1 += __shfl_xor_sync(0xffffffffu, s1, 2);
            if (tig == 0) {
                partial[ch * 64 + wr * 16 + gid] = s0;
                partial[ch * 64 + wr * 16 + gid + 8] = s1;
            }
            __syncthreads();
            if (t < 64) out[n0 + t] = partial[t] + partial[64 + t] + bc0;
        } else {
            #pragma unroll
            for (int nt = 0; nt < 4; nt++) {
                int col = ch * 32 + nt * 8 + tig * 2;
                int r0 = n0 + wr * 16 + gid;
                unsigned u0 = h2u(__floats2half2_rn(fmaxf(acc[nt][0], 0.f), fmaxf(acc[nt][1], 0.f)));
                unsigned u1 = h2u(__floats2half2_rn(fmaxf(acc[nt][2], 0.f), fmaxf(acc[nt][3], 0.f)));
                hh_out[(size_t)r0 * 32 + (col >> 1)] = u0;
                hh_out[(size_t)(r0 + 8) * 32 + (col >> 1)] = u1;
            }
        }
    }
}

extern "C" void kernel_launch(void* const* d_in, const int* in_sizes, int n_in,
                              void* d_out, int out_size)
{
    const float* x   = (const float*)d_in[0];
    const int*   ei  = (const int*)d_in[1];
    const float* Wp  = (const float*)d_in[2];
    const float* bp  = (const float*)d_in[3];
    const float* W1l = (const float*)d_in[4];
    const float* b1l = (const float*)d_in[5];
    const float* W1r = (const float*)d_in[6];
    const float* W2l = (const float*)d_in[7];
    const float* b2l = (const float*)d_in[8];
    const float* W2r = (const float*)d_in[9];
    const float* Wc  = (const float*)d_in[10];
    const float* bc  = (const float*)d_in[11];
    float* out = (float*)d_out;

    const int* src = ei;
    const int* dst = ei + Ee;

    uint4 *hh0, *hh1, *ag;
    int *degi, *off, *cur, *csr, *bsum, *bscan;
    cudaGetSymbolAddress((void**)&hh0, g_hh0);
    cudaGetSymbolAddress((void**)&hh1, g_hh1);
    cudaGetSymbolAddress((void**)&ag, g_ag);
    cudaGetSymbolAddress((void**)&degi, g_degi);
    cudaGetSymbolAddress((void**)&off, g_off);
    cudaGetSymbolAddress((void**)&cur, g_cur);
    cudaGetSymbolAddress((void**)&csr, g_csr);
    cudaGetSymbolAddress((void**)&bsum, g_bsum);
    cudaGetSymbolAddress((void**)&bscan, g_bscan);

    static cudaStream_t s2 = nullptr;
    static cudaEvent_t evFork = nullptr, evJoin = nullptr;
    if (!s2) {
        cudaStreamCreateWithFlags(&s2, cudaStreamNonBlocking);
        cudaEventCreateWithFlags(&evFork, cudaEventDisableTiming);
        cudaEventCreateWithFlags(&evJoin, cudaEventDisableTiming);
        cudaFuncSetAttribute(proj_mma, cudaFuncAttributeMaxDynamicSharedMemorySize, PROJ_SMEM_BYTES);
    }

    // ---- fork: CSR build on side stream, proj on main stream ----
    cudaEventRecord(evFork, 0);
    cudaStreamWaitEvent(s2, evFork, 0);

    cudaMemsetAsync(degi, 0, Nn * sizeof(int), s2);
    deg_kernel<<<(Ee / 4 + 255) / 256, 256, 0, s2>>>(dst, degi);
    scan1<<<NB1K, 256, 0, s2>>>(degi, bsum);
    scan2<<<1, 256, 0, s2>>>(bsum, bscan);
    scan3<<<NB1K, 256, 0, s2>>>(degi, bscan, off, cur);
    place_kernel<<<(Ee / 4 + 255) / 256, 256, 0, s2>>>(src, dst, cur, csr);
    cudaEventRecord(evJoin, s2);

    proj_mma<<<296, 256, PROJ_SMEM_BYTES>>>(x, Wp, bp, hh0);

    // ---- join ----
    cudaStreamWaitEvent(0, evJoin, 0);

    // ---- layer 1 ----
    gather_mean_h<<<(Nn * 32 + 255) / 256, 256>>>(csr, off, degi, hh0, ag);
    sage_mma<false><<<444, 256, SAGE_SMEM_BYTES>>>(hh0, ag, W1l, b1l, W1r,
                                                   (unsigned*)hh1, nullptr, nullptr, nullptr);

    // ---- layer 2 (+ fused classifier) ----
    gather_mean_h<<<(Nn * 32 + 255) / 256, 256>>>(csr, off, degi, hh1, ag);
    sage_mma<true><<<444, 256, SAGE_SMEM_BYTES>>>(hh1, ag, W2l, b2l, W2r,
                                                  nullptr, out, Wc, bc);
}